// round 7
// baseline (speedup 1.0000x reference)
#include <cuda_runtime.h>
#include <cuda_fp16.h>
#include <stdint.h>

// Problem constants (fixed by setup_inputs)
#define NQ   100000
#define HN   32      // neighbors per query
#define KP   15      // kernel points
#define CIN  64
#define COUT 128
#define KC   (KP * CIN)   // 960
#define KP_EXT 1.2f
#define KP_EXT2 (KP_EXT * KP_EXT)   // 1.44

// Scratch (device globals: allocation-free)
__device__ __half g_weighted[(size_t)NQ * KC];   // [N][K*Cin] fp16, ~192 MB
__device__ __half g_wts[KC * COUT];              // [K*Cin][Cout] fp16

__device__ __forceinline__ uint32_t smem_u32(const void* p) {
    uint32_t a;
    asm("{ .reg .u64 t; cvta.to.shared.u64 t, %1; cvt.u32.u64 %0, t; }"
        : "=r"(a) : "l"(p));
    return a;
}
__device__ __forceinline__ void ldm_x4(uint32_t& r0, uint32_t& r1,
                                       uint32_t& r2, uint32_t& r3,
                                       uint32_t addr) {
    asm volatile("ldmatrix.sync.aligned.m8n8.x4.shared.b16 {%0,%1,%2,%3}, [%4];"
                 : "=r"(r0), "=r"(r1), "=r"(r2), "=r"(r3) : "r"(addr));
}
__device__ __forceinline__ void ldm_x4_t(uint32_t& r0, uint32_t& r1,
                                         uint32_t& r2, uint32_t& r3,
                                         uint32_t addr) {
    asm volatile("ldmatrix.sync.aligned.m8n8.x4.trans.shared.b16 {%0,%1,%2,%3}, [%4];"
                 : "=r"(r0), "=r"(r1), "=r"(r2), "=r"(r3) : "r"(addr));
}
__device__ __forceinline__ void mma16816(float& c0, float& c1, float& c2, float& c3,
                                         uint32_t a0, uint32_t a1, uint32_t a2, uint32_t a3,
                                         uint32_t b0, uint32_t b1) {
    asm volatile(
        "mma.sync.aligned.m16n8k16.row.col.f32.f16.f16.f32 "
        "{%0,%1,%2,%3}, {%4,%5,%6,%7}, {%8,%9}, {%0,%1,%2,%3};"
        : "+f"(c0), "+f"(c1), "+f"(c2), "+f"(c3)
        : "r"(a0), "r"(a1), "r"(a2), "r"(a3), "r"(b0), "r"(b1));
}

// ---------------------------------------------------------------------------
// Kernel 0: convert wts fp32 -> fp16
// ---------------------------------------------------------------------------
__global__ void convert_wts_kernel(const float* __restrict__ wts) {
    int i = blockIdx.x * blockDim.x + threadIdx.x;
    if (i < KC * COUT) g_wts[i] = __float2half(wts[i]);
}

// ---------------------------------------------------------------------------
// Kernel 1: weights + weighted aggregation, aggregation done with HMMA.
// Per warp/query: A = w[k][h] fp16 [16x32] (row 15 zero), B = staged
// features [32x64] fp16; weighted[16x64] = A x B via 16 x mma.m16n8k16.
// Inactive neighbors contribute exactly 0 (w stored as 0), so no per-k
// masks/ballots/bit-loops are needed.
// ---------------------------------------------------------------------------
#define A_ST 40   // halves per A row (32 data + 8 pad) -> conflict-free ldmatrix
#define F_ST 36   // half2 per feature row (32 data + 4 pad) = 144B rows

__global__ void __launch_bounds__(128, 8) weight_kernel(
    const float* __restrict__ qpts,
    const float* __restrict__ spts,
    const int*   __restrict__ nidx,
    const float* __restrict__ feats,
    const float* __restrict__ kpts,
    int nq)
{
    __shared__ __half2 Fs[4][HN * F_ST];   // 4 * 4.6KB = 18.4KB
    __shared__ __half  Aw[4][16 * A_ST];   // 4 * 1.25KB = 5KB
    __shared__ float4  skp[KP];

    int tid = threadIdx.x;
    if (tid < KP) {
        float kx = kpts[3 * tid + 0];
        float ky = kpts[3 * tid + 1];
        float kz = kpts[3 * tid + 2];
        skp[tid] = make_float4(kx, ky, kz, kx * kx + ky * ky + kz * kz);
    }
    // Zero-init feature stage once (stale bits could be NaN; 0 * NaN = NaN).
    for (int i = tid; i < 4 * HN * F_ST; i += 128)
        ((__half2*)Fs)[i] = __half2(__float2half(0.f), __float2half(0.f));
    __syncthreads();

    int warp = tid >> 5;
    int lane = tid & 31;
    const float inv_ext = 1.0f / KP_EXT;
    int qbase = blockIdx.x * 16 + warp * 4;

    const float2* __restrict__ f2 = (const float2*)feats;
    __half2* FsW = Fs[warp];
    __half*  AwW = Aw[warp];
    __half2* outp = (__half2*)g_weighted;

    #pragma unroll 1
    for (int qi = 0; qi < 4; qi++) {
        int q = qbase + qi;
        if (q >= nq) return;   // warp-uniform

        // ---- weights: lane owns neighbor h = lane; store fp16 into A ----
        int idx = nidx[q * HN + lane];
        float qx = qpts[q * 3 + 0];
        float qy = qpts[q * 3 + 1];
        float qz = qpts[q * 3 + 2];
        float px = spts[idx * 3 + 0] - qx;
        float py = spts[idx * 3 + 1] - qy;
        float pz = spts[idx * 3 + 2] - qz;
        float pp = px * px + py * py + pz * pz;

        float wmax = 0.0f;
        #pragma unroll
        for (int k = 0; k < KP; k++) {
            float4 kv = skp[k];
            float t  = fmaf(px, kv.x, fmaf(py, kv.y, pz * kv.z));
            float d2 = fmaf(-2.0f, t, pp + kv.w);
            float wv = 0.0f;
            if (d2 < KP_EXT2)
                wv = 1.0f - sqrtf(fmaxf(d2, 0.0f)) * inv_ext;
            wmax = fmaxf(wmax, wv);
            AwW[k * A_ST + lane] = __float2half(wv);
        }
        AwW[15 * A_ST + lane] = __float2half(0.0f);   // pad row
        unsigned active_h = __ballot_sync(0xffffffffu, wmax > 0.0f);

        // ---- stage active neighbor features (fp16, MLP ~32) ----
        __syncwarp();
        #pragma unroll
        for (int h = 0; h < HN; h++) {
            if ((active_h >> h) & 1u) {               // warp-uniform predicate
                int ih = __shfl_sync(0xffffffffu, idx, h);
                float2 f = f2[(size_t)ih * 32 + lane];
                FsW[h * F_ST + lane] = __floats2half2_rn(f.x, f.y);
            }
        }
        __syncwarp();

        // ---- A fragments: [16 k][32 h], two k16 halves ----
        uint32_t a[2][4];
        #pragma unroll
        for (int s = 0; s < 2; s++) {
            uint32_t addr = smem_u32(
                AwW + (lane & 15) * A_ST + s * 16 + (lane >> 4) * 8);
            ldm_x4(a[s][0], a[s][1], a[s][2], a[s][3], addr);
        }

        // ---- B fragments + MMA: weighted[16x64] = A x B ----
        float c[8][4];
        #pragma unroll
        for (int t = 0; t < 8; t++)
            #pragma unroll
            for (int j = 0; j < 4; j++) c[t][j] = 0.0f;

        const __half* Fh = (const __half*)FsW;        // [32][72] halves
        #pragma unroll
        for (int s = 0; s < 2; s++) {
            #pragma unroll
            for (int g = 0; g < 4; g++) {
                uint32_t addr = smem_u32(
                    Fh + (s * 16 + (lane & 15)) * (2 * F_ST)
                       + g * 16 + (lane >> 4) * 8);
                uint32_t r0, r1, r2, r3;
                ldm_x4_t(r0, r1, r2, r3, addr);
                mma16816(c[2*g  ][0], c[2*g  ][1], c[2*g  ][2], c[2*g  ][3],
                         a[s][0], a[s][1], a[s][2], a[s][3], r0, r1);
                mma16816(c[2*g+1][0], c[2*g+1][1], c[2*g+1][2], c[2*g+1][3],
                         a[s][0], a[s][1], a[s][2], a[s][3], r2, r3);
            }
        }

        // ---- epilogue: c rows = k (gid, gid+8), cols = t*8 + tig*2 ----
        int gid = lane >> 2, tig = lane & 3;
        size_t qb = (size_t)q * (KC / 2);
        #pragma unroll
        for (int t = 0; t < 8; t++) {
            int col2 = t * 4 + tig;                       // half2 col index
            outp[qb + gid * 32 + col2] = __floats2half2_rn(c[t][0], c[t][1]);
            if (gid + 8 < KP)
                outp[qb + (gid + 8) * 32 + col2] =
                    __floats2half2_rn(c[t][2], c[t][3]);
        }
    }
}

// ---------------------------------------------------------------------------
// Kernel 2: GEMM out[N][128] = weighted[N][960] (f16) x wts[960][128] (f16)
// 128x128 tile, 8 warps (64x32 each), m16n8k16 HMMA, 2-stage cp.async pipeline.
// ---------------------------------------------------------------------------
__device__ __forceinline__ void cp16(uint32_t dst, const void* src, bool pred) {
    int sz = pred ? 16 : 0;
    asm volatile("cp.async.cg.shared.global [%0], [%1], 16, %2;"
                 :: "r"(dst), "l"(src), "r"(sz) : "memory");
}

#define AS_STRIDE 48    // halves per A row (32 data + 16 pad)
#define BS_STRIDE 136   // halves per B row (128 data + 8 pad)
#define NKT (KC / 32)   // 30 k-iterations

__global__ void __launch_bounds__(256) gemm_kernel(float* __restrict__ out, int nq) {
    __shared__ __half As[2][128 * AS_STRIDE];
    __shared__ __half Bs[2][32 * BS_STRIDE];

    int tid  = threadIdx.x;
    int wid  = tid >> 5;
    int lane = tid & 31;
    int wm = wid >> 2;   // 0..1  (64 rows each)
    int wn = wid & 3;    // 0..3  (32 cols each)
    int m0 = blockIdx.x * 128;

    int arow[2], aseg[2], brow[2], bseg[2];
    #pragma unroll
    for (int i = 0; i < 2; i++) {
        int chunk = tid + i * 256;
        arow[i] = chunk >> 2;  aseg[i] = chunk & 3;
        brow[i] = chunk >> 4;  bseg[i] = chunk & 15;
    }

    float c[4][4][4];
    #pragma unroll
    for (int i = 0; i < 4; i++)
        #pragma unroll
        for (int j = 0; j < 4; j++)
            #pragma unroll
            for (int t = 0; t < 4; t++) c[i][j][t] = 0.0f;

    int lrow  = lane & 15;
    int lcolh = (lane >> 4) * 8;

    auto issue = [&](int kt) {
        int st = kt & 1;
        #pragma unroll
        for (int i = 0; i < 2; i++) {
            int rg = m0 + arow[i];
            bool ok = (rg < nq);
            const __half* src = g_weighted +
                (size_t)(ok ? rg : 0) * KC + kt * 32 + aseg[i] * 8;
            cp16(smem_u32(&As[st][arow[i] * AS_STRIDE + aseg[i] * 8]), src, ok);
        }
        #pragma unroll
        for (int i = 0; i < 2; i++) {
            const __half* src = g_wts + (kt * 32 + brow[i]) * COUT + bseg[i] * 8;
            cp16(smem_u32(&Bs[st][brow[i] * BS_STRIDE + bseg[i] * 8]), src, true);
        }
    };

    issue(0);
    asm volatile("cp.async.commit_group;" ::: "memory");

    for (int kt = 0; kt < NKT; kt++) {
        if (kt + 1 < NKT) issue(kt + 1);
        asm volatile("cp.async.commit_group;" ::: "memory");
        asm volatile("cp.async.wait_group 1;" ::: "memory");
        __syncthreads();

        int st = kt & 1;
        #pragma unroll
        for (int ks = 0; ks < 2; ks++) {
            uint32_t a[4][4], b[4][2];
            #pragma unroll
            for (int im = 0; im < 4; im++) {
                uint32_t addr = smem_u32(
                    &As[st][(wm * 64 + im * 16 + lrow) * AS_STRIDE + ks * 16 + lcolh]);
                ldm_x4(a[im][0], a[im][1], a[im][2], a[im][3], addr);
            }
            #pragma unroll
            for (int ip = 0; ip < 2; ip++) {
                uint32_t addr = smem_u32(
                    &Bs[st][(ks * 16 + lrow) * BS_STRIDE + wn * 32 + ip * 16 + lcolh]);
                uint32_t r0, r1, r2, r3;
                ldm_x4_t(r0, r1, r2, r3, addr);
                b[ip * 2 + 0][0] = r0; b[ip * 2 + 0][1] = r1;
                b[ip * 2 + 1][0] = r2; b[ip * 2 + 1][1] = r3;
            }
            #pragma unroll
            for (int im = 0; im < 4; im++)
                #pragma unroll
                for (int in = 0; in < 4; in++)
                    mma16816(c[im][in][0], c[im][in][1], c[im][in][2], c[im][in][3],
                             a[im][0], a[im][1], a[im][2], a[im][3],
                             b[in][0], b[in][1]);
        }
        __syncthreads();
    }

    // Epilogue
    int gid = lane >> 2, tig = lane & 3;
    #pragma unroll
    for (int im = 0; im < 4; im++) {
        #pragma unroll
        for (int in = 0; in < 4; in++) {
            int row = m0 + wm * 64 + im * 16 + gid;
            int col = wn * 32 + in * 8 + tig * 2;
            if (row < nq) {
                float2 v0 = make_float2(c[im][in][0], c[im][in][1]);
                *(float2*)(out + (size_t)row * COUT + col) = v0;
            }
            if (row + 8 < nq) {
                float2 v1 = make_float2(c[im][in][2], c[im][in][3]);
                *(float2*)(out + (size_t)(row + 8) * COUT + col) = v1;
            }
        }
    }
}

// ---------------------------------------------------------------------------
extern "C" void kernel_launch(void* const* d_in, const int* in_sizes, int n_in,
                              void* d_out, int out_size) {
    const float* qp = (const float*)d_in[0];   // query_points   [N,3]
    const float* sp = (const float*)d_in[1];   // support_points [M,3]
    const int*   ni = (const int*)  d_in[2];   // neighbors_idx  [N,32]
    const float* ft = (const float*)d_in[3];   // features       [M,64]
    const float* kp = (const float*)d_in[4];   // kernel_points  [15,3]
    const float* wt = (const float*)d_in[5];   // wts            [15,64,128]
    float* out = (float*)d_out;

    int nq = in_sizes[0] / 3;

    // weight_kernel first => it is the kernel ncu captures.
    weight_kernel<<<(nq + 15) / 16, 128>>>(qp, sp, ni, ft, kp, nq);
    convert_wts_kernel<<<(KC * COUT + 255) / 256, 256>>>(wt);
    gemm_kernel<<<(nq + 127) / 128, 256>>>(out, nq);
}

// round 8
// speedup vs baseline: 1.1396x; 1.1396x over previous
#include <cuda_runtime.h>
#include <cuda_fp16.h>
#include <stdint.h>

// Problem constants (fixed by setup_inputs)
#define NQ   100000
#define HN   32      // neighbors per query
#define KP   15      // kernel points
#define CIN  64
#define COUT 128
#define KC   (KP * CIN)   // 960
#define KP_EXT 1.2f
#define KP_EXT2 (KP_EXT * KP_EXT)   // 1.44

// Scratch (device globals: allocation-free)
__device__ __half g_weighted[(size_t)NQ * KC];   // [N][K*Cin] fp16, ~192 MB
__device__ __half g_wts[KC * COUT];              // [K*Cin][Cout] fp16

__device__ __forceinline__ uint32_t smem_u32(const void* p) {
    uint32_t a;
    asm("{ .reg .u64 t; cvta.to.shared.u64 t, %1; cvt.u32.u64 %0, t; }"
        : "=r"(a) : "l"(p));
    return a;
}

// ---------------------------------------------------------------------------
// Kernel 0: convert wts fp32 -> fp16
// ---------------------------------------------------------------------------
__global__ void convert_wts_kernel(const float* __restrict__ wts) {
    int i = blockIdx.x * blockDim.x + threadIdx.x;
    if (i < KC * COUT) g_wts[i] = __float2half(wts[i]);
}

// ---------------------------------------------------------------------------
// Kernel 1: weights + sparse weighted feature aggregation (round-6 winner,
// occupancy raised 10 -> 12 blocks/SM: 40 -> 48 resident warps theoretical).
// fp16 feature staging (16KB/block); fp32 accumulation.
// ---------------------------------------------------------------------------
__global__ void __launch_bounds__(128, 12) weight_kernel(
    const float* __restrict__ qpts,
    const float* __restrict__ spts,
    const int*   __restrict__ nidx,
    const float* __restrict__ feats,
    const float* __restrict__ kpts,
    int nq)
{
    __shared__ __half2 Fs[4][HN * 32];  // [warp][h][c-pair]  4*4KB = 16KB
    __shared__ float4 skp[KP];          // (kx, ky, kz, |kp|^2)

    int tid = threadIdx.x;
    if (tid < KP) {
        float kx = kpts[3 * tid + 0];
        float ky = kpts[3 * tid + 1];
        float kz = kpts[3 * tid + 2];
        skp[tid] = make_float4(kx, ky, kz, kx * kx + ky * ky + kz * kz);
    }
    __syncthreads();

    int warp = tid >> 5;
    int lane = tid & 31;
    const float inv_ext = 1.0f / KP_EXT;
    int qbase = blockIdx.x * 16 + warp * 4;

    const float2* __restrict__ f2 = (const float2*)feats;
    __half2* FsW = Fs[warp];
    __half2* outp = (__half2*)g_weighted;

    #pragma unroll 1
    for (int qi = 0; qi < 4; qi++) {
        int q = qbase + qi;
        if (q >= nq) return;   // warp-uniform

        // ---- weights: lane owns neighbor h = lane ----
        int idx = nidx[q * HN + lane];
        float qx = qpts[q * 3 + 0];
        float qy = qpts[q * 3 + 1];
        float qz = qpts[q * 3 + 2];
        float px = spts[idx * 3 + 0] - qx;
        float py = spts[idx * 3 + 1] - qy;
        float pz = spts[idx * 3 + 2] - qz;
        float pp = px * px + py * py + pz * pz;

        float    w[KP];
        unsigned m[KP];
        unsigned active_h = 0;
        #pragma unroll
        for (int k = 0; k < KP; k++) {
            float4 kv = skp[k];
            float t  = fmaf(px, kv.x, fmaf(py, kv.y, pz * kv.z));
            float d2 = fmaf(-2.0f, t, pp + kv.w);
            float wv = 0.0f;
            if (d2 < KP_EXT2)
                wv = 1.0f - sqrtf(fmaxf(d2, 0.0f)) * inv_ext;
            w[k] = wv;
            m[k] = __ballot_sync(0xffffffffu, wv > 0.0f);
            active_h |= m[k];
        }

        // ---- Phase A: stage active neighbor features to smem (fp16) ----
        __syncwarp();
        #pragma unroll
        for (int h = 0; h < HN; h++) {
            if ((active_h >> h) & 1u) {               // warp-uniform predicate
                int ih = __shfl_sync(0xffffffffu, idx, h);
                float2 f = f2[(size_t)ih * 32 + lane];
                FsW[h * 32 + lane] = __floats2half2_rn(f.x, f.y);
            }
        }
        __syncwarp();

        // ---- Phase B: sparse per-k accumulation (fp32 acc) ----
        #pragma unroll
        for (int k = 0; k < KP; k++) {
            float ax = 0.0f, ay = 0.0f;
            unsigned mm = m[k];
            while (mm) {
                int h = __ffs(mm) - 1;
                mm &= mm - 1;
                float wk = __shfl_sync(0xffffffffu, w[k], h);
                float2 f = __half22float2(FsW[h * 32 + lane]);
                ax = fmaf(wk, f.x, ax);
                ay = fmaf(wk, f.y, ay);
            }
            outp[(size_t)q * (KC / 2) + k * 32 + lane] = __floats2half2_rn(ax, ay);
        }
    }
}

// ---------------------------------------------------------------------------
// Kernel 2: GEMM out[N][128] = weighted[N][960] (f16) x wts[960][128] (f16)
// 128x128 tile, 8 warps (64x32 each), m16n8k16 HMMA, 2-stage cp.async pipeline.
// ---------------------------------------------------------------------------
__device__ __forceinline__ void ldm_x4(uint32_t& r0, uint32_t& r1,
                                       uint32_t& r2, uint32_t& r3,
                                       uint32_t addr) {
    asm volatile("ldmatrix.sync.aligned.m8n8.x4.shared.b16 {%0,%1,%2,%3}, [%4];"
                 : "=r"(r0), "=r"(r1), "=r"(r2), "=r"(r3) : "r"(addr));
}
__device__ __forceinline__ void ldm_x4_t(uint32_t& r0, uint32_t& r1,
                                         uint32_t& r2, uint32_t& r3,
                                         uint32_t addr) {
    asm volatile("ldmatrix.sync.aligned.m8n8.x4.trans.shared.b16 {%0,%1,%2,%3}, [%4];"
                 : "=r"(r0), "=r"(r1), "=r"(r2), "=r"(r3) : "r"(addr));
}
__device__ __forceinline__ void mma16816(float& c0, float& c1, float& c2, float& c3,
                                         uint32_t a0, uint32_t a1, uint32_t a2, uint32_t a3,
                                         uint32_t b0, uint32_t b1) {
    asm volatile(
        "mma.sync.aligned.m16n8k16.row.col.f32.f16.f16.f32 "
        "{%0,%1,%2,%3}, {%4,%5,%6,%7}, {%8,%9}, {%0,%1,%2,%3};"
        : "+f"(c0), "+f"(c1), "+f"(c2), "+f"(c3)
        : "r"(a0), "r"(a1), "r"(a2), "r"(a3), "r"(b0), "r"(b1));
}
__device__ __forceinline__ void cp16(uint32_t dst, const void* src, bool pred) {
    int sz = pred ? 16 : 0;
    asm volatile("cp.async.cg.shared.global [%0], [%1], 16, %2;"
                 :: "r"(dst), "l"(src), "r"(sz) : "memory");
}

#define AS_STRIDE 48    // halves per A row (32 data + 16 pad)
#define BS_STRIDE 136   // halves per B row (128 data + 8 pad)
#define NKT (KC / 32)   // 30 k-iterations

__global__ void __launch_bounds__(256) gemm_kernel(float* __restrict__ out, int nq) {
    __shared__ __half As[2][128 * AS_STRIDE];
    __shared__ __half Bs[2][32 * BS_STRIDE];

    int tid  = threadIdx.x;
    int wid  = tid >> 5;
    int lane = tid & 31;
    int wm = wid >> 2;   // 0..1  (64 rows each)
    int wn = wid & 3;    // 0..3  (32 cols each)
    int m0 = blockIdx.x * 128;

    int arow[2], aseg[2], brow[2], bseg[2];
    #pragma unroll
    for (int i = 0; i < 2; i++) {
        int chunk = tid + i * 256;
        arow[i] = chunk >> 2;  aseg[i] = chunk & 3;
        brow[i] = chunk >> 4;  bseg[i] = chunk & 15;
    }

    float c[4][4][4];
    #pragma unroll
    for (int i = 0; i < 4; i++)
        #pragma unroll
        for (int j = 0; j < 4; j++)
            #pragma unroll
            for (int t = 0; t < 4; t++) c[i][j][t] = 0.0f;

    int lrow  = lane & 15;
    int lcolh = (lane >> 4) * 8;

    auto issue = [&](int kt) {
        int st = kt & 1;
        #pragma unroll
        for (int i = 0; i < 2; i++) {
            int rg = m0 + arow[i];
            bool ok = (rg < nq);
            const __half* src = g_weighted +
                (size_t)(ok ? rg : 0) * KC + kt * 32 + aseg[i] * 8;
            cp16(smem_u32(&As[st][arow[i] * AS_STRIDE + aseg[i] * 8]), src, ok);
        }
        #pragma unroll
        for (int i = 0; i < 2; i++) {
            const __half* src = g_wts + (kt * 32 + brow[i]) * COUT + bseg[i] * 8;
            cp16(smem_u32(&Bs[st][brow[i] * BS_STRIDE + bseg[i] * 8]), src, true);
        }
    };

    issue(0);
    asm volatile("cp.async.commit_group;" ::: "memory");

    for (int kt = 0; kt < NKT; kt++) {
        if (kt + 1 < NKT) issue(kt + 1);
        asm volatile("cp.async.commit_group;" ::: "memory");
        asm volatile("cp.async.wait_group 1;" ::: "memory");
        __syncthreads();

        int st = kt & 1;
        #pragma unroll
        for (int ks = 0; ks < 2; ks++) {
            uint32_t a[4][4], b[4][2];
            #pragma unroll
            for (int im = 0; im < 4; im++) {
                uint32_t addr = smem_u32(
                    &As[st][(wm * 64 + im * 16 + lrow) * AS_STRIDE + ks * 16 + lcolh]);
                ldm_x4(a[im][0], a[im][1], a[im][2], a[im][3], addr);
            }
            #pragma unroll
            for (int ip = 0; ip < 2; ip++) {
                uint32_t addr = smem_u32(
                    &Bs[st][(ks * 16 + lrow) * BS_STRIDE + wn * 32 + ip * 16 + lcolh]);
                uint32_t r0, r1, r2, r3;
                ldm_x4_t(r0, r1, r2, r3, addr);
                b[ip * 2 + 0][0] = r0; b[ip * 2 + 0][1] = r1;
                b[ip * 2 + 1][0] = r2; b[ip * 2 + 1][1] = r3;
            }
            #pragma unroll
            for (int im = 0; im < 4; im++)
                #pragma unroll
                for (int in = 0; in < 4; in++)
                    mma16816(c[im][in][0], c[im][in][1], c[im][in][2], c[im][in][3],
                             a[im][0], a[im][1], a[im][2], a[im][3],
                             b[in][0], b[in][1]);
        }
        __syncthreads();
    }

    // Epilogue
    int gid = lane >> 2, tig = lane & 3;
    #pragma unroll
    for (int im = 0; im < 4; im++) {
        #pragma unroll
        for (int in = 0; in < 4; in++) {
            int row = m0 + wm * 64 + im * 16 + gid;
            int col = wn * 32 + in * 8 + tig * 2;
            if (row < nq) {
                float2 v0 = make_float2(c[im][in][0], c[im][in][1]);
                *(float2*)(out + (size_t)row * COUT + col) = v0;
            }
            if (row + 8 < nq) {
                float2 v1 = make_float2(c[im][in][2], c[im][in][3]);
                *(float2*)(out + (size_t)(row + 8) * COUT + col) = v1;
            }
        }
    }
}

// ---------------------------------------------------------------------------
extern "C" void kernel_launch(void* const* d_in, const int* in_sizes, int n_in,
                              void* d_out, int out_size) {
    const float* qp = (const float*)d_in[0];   // query_points   [N,3]
    const float* sp = (const float*)d_in[1];   // support_points [M,3]
    const int*   ni = (const int*)  d_in[2];   // neighbors_idx  [N,32]
    const float* ft = (const float*)d_in[3];   // features       [M,64]
    const float* kp = (const float*)d_in[4];   // kernel_points  [15,3]
    const float* wt = (const float*)d_in[5];   // wts            [15,64,128]
    float* out = (float*)d_out;

    int nq = in_sizes[0] / 3;

    // weight_kernel first => it is the kernel ncu captures.
    weight_kernel<<<(nq + 15) / 16, 128>>>(qp, sp, ni, ft, kp, nq);
    convert_wts_kernel<<<(KC * COUT + 255) / 256, 256>>>(wt);
    gemm_kernel<<<(nq + 127) / 128, 256>>>(out, nq);
}